// round 4
// baseline (speedup 1.0000x reference)
#include <cuda_runtime.h>

#define NMOV   4096
#define NPHYS  4096
#define BLOCK  256
#define NCTA   148
#define NWARPS (NCTA * (BLOCK / 32))   // 1184
#define GW     34
#define NCELL  (GW * GW)               // 1156
#define INV_CW (1.0f / 16.0f)
#define ORG    (-272.0f)
#define SCAN_C 5                       // 5*256 = 1280 >= NCELL

__device__ int      g_cellCnt[NCELL];   // zero-init; re-zeroed by last block each launch
__device__ int      g_cellFill[NCELL];  // zero-init; re-zeroed by last block each launch
__device__ int      g_cellStart[NCELL];
__device__ int      g_cellOf[NMOV];
__device__ float4   g_pt[NMOV];         // {ax, bx, ay, by} per point
__device__ float4   g_sorted[NMOV];
__device__ float    g_partials[NCTA];
__device__ unsigned g_bar[3];           // spin barriers; reset by last block
__device__ unsigned g_ticket;           // reset by last block

__device__ __forceinline__ void grid_barrier(int k)
{
    __syncthreads();
    if (threadIdx.x == 0) {
        __threadfence();
        atomicAdd(&g_bar[k], 1u);
        while (atomicAdd(&g_bar[k], 0u) < NCTA) __nanosleep(64);
        __threadfence();
    }
    __syncthreads();
}

__global__ __launch_bounds__(BLOCK) void notch_binned(
    const float* __restrict__ pos,
    const float* __restrict__ sx,
    const float* __restrict__ sy,
    float* __restrict__ out)
{
    __shared__ int   wsum[8];
    __shared__ float rsum[8];
    __shared__ bool  isLast;

    const int tid = threadIdx.x;
    const int gid = blockIdx.x * BLOCK + tid;
    const int lane = tid & 31;
    const int wid  = tid >> 5;

    // ---- Phase A: per-point corner data + cell id + histogram ----
    if (gid < NMOV) {
        float x = pos[gid], y = pos[NPHYS + gid];
        float hx = 0.5f * sx[gid], hy = 0.5f * sy[gid];
        g_pt[gid] = make_float4(x - hx, x + hx, y - hy, y + hy);
        int cx = (int)floorf((x - ORG) * INV_CW);
        int cy = (int)floorf((y - ORG) * INV_CW);
        cx = min(max(cx, 0), GW - 1);
        cy = min(max(cy, 0), GW - 1);
        int cell = cy * GW + cx;
        g_cellOf[gid] = cell;
        atomicAdd(&g_cellCnt[cell], 1);
    }
    grid_barrier(0);

    // ---- Phase B: exclusive scan of cell counts (CTA 0 only) ----
    if (blockIdx.x == 0) {
        int base = tid * SCAN_C;
        int loc[SCAN_C];
        int run = 0;
#pragma unroll
        for (int r = 0; r < SCAN_C; ++r) {
            int c = base + r;
            int v = (c < NCELL) ? g_cellCnt[c] : 0;
            loc[r] = run; run += v;
        }
        int inc = run;
#pragma unroll
        for (int off = 1; off < 32; off <<= 1) {
            int n = __shfl_up_sync(0xFFFFFFFFu, inc, off);
            if (lane >= off) inc += n;
        }
        if (lane == 31) wsum[wid] = inc;
        __syncthreads();
        if (tid < 32) {
            int v = (tid < 8) ? wsum[tid] : 0;
            int s = v;
#pragma unroll
            for (int off = 1; off < 8; off <<= 1) {
                int n = __shfl_up_sync(0xFFFFFFFFu, s, off);
                if (lane >= off) s += n;
            }
            if (tid < 8) wsum[tid] = s - v;   // exclusive warp offsets
        }
        __syncthreads();
        int ex = wsum[wid] + inc - run;       // exclusive offset of this thread's chunk
#pragma unroll
        for (int r = 0; r < SCAN_C; ++r) {
            int c = base + r;
            if (c < NCELL) g_cellStart[c] = ex + loc[r];
        }
    }
    grid_barrier(1);

    // ---- Phase C: scatter points into cell-sorted order ----
    if (gid < NMOV) {
        int cell = g_cellOf[gid];
        int slot = g_cellStart[cell] + atomicAdd(&g_cellFill[cell], 1);
        g_sorted[slot] = g_pt[gid];
    }
    grid_barrier(2);

    // ---- Phase D: neighbor-cell pair accumulation (one warp per point) ----
    float acc = 0.0f;
    const int warp = blockIdx.x * (BLOCK / 32) + wid;
    for (int i = warp; i < NMOV; i += NWARPS) {
        const float4 pi = g_pt[i];
        const int cell = g_cellOf[i];
        const int cx = cell % GW, cy = cell / GW;
        const int x0 = max(cx - 1, 0), x1 = min(cx + 1, GW - 1);
        const int y0 = max(cy - 1, 0), y1 = min(cy + 1, GW - 1);
        for (int yy = y0; yy <= y1; ++yy) {
            int c0 = yy * GW + x0;
            int c1 = yy * GW + x1;
            int s = g_cellStart[c0];
            int e = g_cellStart[c1] + g_cellCnt[c1];   // 3 cells are contiguous
            for (int k = s + lane; k < e; k += 32) {
                float4 t = g_sorted[k];
                float dx = fmaxf(fmaxf(pi.x - t.y, t.x - pi.y), 0.0f);
                float dy = fmaxf(fmaxf(pi.z - t.w, t.z - pi.w), 0.0f);
                float p  = fmaxf(2.0f - (dx + dy), 0.0f);
                acc = fmaf(p, p, acc);
            }
        }
    }

    // ---- Phase E: block reduce, ticket, final reduce by last block ----
#pragma unroll
    for (int off = 16; off > 0; off >>= 1)
        acc += __shfl_xor_sync(0xFFFFFFFFu, acc, off);
    if (lane == 0) rsum[wid] = acc;
    __syncthreads();
    if (tid < 32) {
        float v = (tid < 8) ? rsum[tid] : 0.0f;
#pragma unroll
        for (int off = 4; off > 0; off >>= 1)
            v += __shfl_xor_sync(0xFFFFFFFFu, v, off);
        if (tid == 0) {
            g_partials[blockIdx.x] = v;
            __threadfence();
            unsigned t = atomicAdd(&g_ticket, 1u);
            isLast = (t == NCTA - 1);
        }
    }
    __syncthreads();

    if (isLast) {
        __threadfence();
        float v = (tid < NCTA) ? g_partials[tid] : 0.0f;
#pragma unroll
        for (int off = 16; off > 0; off >>= 1)
            v += __shfl_xor_sync(0xFFFFFFFFu, v, off);
        if (lane == 0) rsum[wid] = v;
        __syncthreads();
        if (tid == 0) {
            float s = 0.0f;
#pragma unroll
            for (int w = 0; w < 8; ++w) s += rsum[w];
            // Symmetric search counts each unordered pair twice + N self terms (p=2 -> 4).
            out[0] = 0.5f * (s - 4.0f * (float)NMOV);
        }
        // Reset all mutable state for the next graph replay.
        for (int c = tid; c < NCELL; c += BLOCK) {
            g_cellCnt[c] = 0;
            g_cellFill[c] = 0;
        }
        if (tid < 3) g_bar[tid] = 0;
        if (tid == 0) g_ticket = 0;
    }
}

extern "C" void kernel_launch(void* const* d_in, const int* in_sizes, int n_in,
                              void* d_out, int out_size)
{
    (void)in_sizes; (void)n_in; (void)out_size;
    const float* pos = (const float*)d_in[0];
    // d_in[1] is macro_mask (bool) — all-true, unused by the computation.
    const float* sx  = (const float*)d_in[2];
    const float* sy  = (const float*)d_in[3];
    float* out = (float*)d_out;

    notch_binned<<<NCTA, BLOCK>>>(pos, sx, sy, out);
}

// round 6
// speedup vs baseline: 1.9552x; 1.9552x over previous
#include <cuda_runtime.h>

#define NMOV  4096
#define NPHYS 4096
#define BLOCK 256
#define ITILE 512                      // i-tile width (2 rows per thread)
#define T     8                        // 512-wide tiles per dimension
#define NT    (T * (T + 1) / 2)        // 36 triangular tiles
#define JSPL  16
#define CHUNK (ITILE / JSPL)           // 32 j's per CTA
#define NCTA  (NT * JSPL)              // 576

__device__ float g_partials[NCTA];
__device__ unsigned int g_count;       // zero-init; reset by last block each launch

__global__ __launch_bounds__(BLOCK) void notch_rt2(
    const float* __restrict__ pos,
    const float* __restrict__ sx,
    const float* __restrict__ sy,
    float* __restrict__ out)
{
    // Per-j tile entry: {bjx+2, 2-ajx, bjy, -ajy}
    __shared__ float4 tile[CHUNK];
    __shared__ float warpsum[BLOCK / 32];
    __shared__ bool isLast;

    const int tid = threadIdx.x;
    const int l   = blockIdx.x / JSPL;       // triangular tile index
    const int ch  = blockIdx.x % JSPL;       // j-chunk

    // linear tile index -> (it, jt), jt >= it (T=8)
    int row = 0, rem = l, cnt = T;
    while (rem >= cnt) { rem -= cnt; ++row; --cnt; }
    const int it = row;
    const int jt = row + rem;

    const float* __restrict__ x = pos;
    const float* __restrict__ y = pos + NPHYS;

    // Two i rows per thread (corner form)
    const int i0 = it * ITILE + tid;
    const int i1 = i0 + BLOCK;
    const float hx0 = 0.5f * sx[i0], hy0 = 0.5f * sy[i0];
    const float hx1 = 0.5f * sx[i1], hy1 = 0.5f * sy[i1];
    const float x0 = x[i0], y0 = y[i0];
    const float x1 = x[i1], y1 = y[i1];
    const float a0x = x0 - hx0, b0x = x0 + hx0, a0y = y0 - hy0, b0y = y0 + hy0;
    const float a1x = x1 - hx1, b1x = x1 + hx1, a1y = y1 - hy1, b1y = y1 + hy1;

    // Fill j-chunk (32 entries, warp 0)
    if (tid < CHUNK) {
        const int j = jt * ITILE + ch * CHUNK + tid;
        const float hxj = 0.5f * sx[j], hyj = 0.5f * sy[j];
        const float xj = x[j], yj = y[j];
        tile[tid] = make_float4((xj + hxj) + 2.0f,   // bjx + 2
                                2.0f - (xj - hxj),   // 2 - ajx
                                yj + hyj,            // bjy
                                -(yj - hyj));        // -ajy
    }
    __syncthreads();

    float acc0 = 0.0f, acc1 = 0.0f;
#pragma unroll 8
    for (int k = 0; k < CHUNK; ++k) {
        const float4 t = tile[k];
        // i0:  rx' = min(bjx+2-aix, bix+2-ajx, 2) = 2-dx ; ry = min(bjy-aiy, biy-ajy, 0) = -dy
        {
            float rx = fminf(fminf(t.x - a0x, b0x + t.y), 2.0f);
            float ry = fminf(fminf(t.z - a0y, b0y + t.w), 0.0f);
            float p  = fmaxf(rx + ry, 0.0f);
            acc0 = fmaf(p, p, acc0);
        }
        // i1
        {
            float rx = fminf(fminf(t.x - a1x, b1x + t.y), 2.0f);
            float ry = fminf(fminf(t.z - a1y, b1y + t.w), 0.0f);
            float p  = fmaxf(rx + ry, 0.0f);
            acc1 = fmaf(p, p, acc1);
        }
    }
    float acc = acc0 + acc1;

    // Deterministic block reduce
#pragma unroll
    for (int off = 16; off > 0; off >>= 1)
        acc += __shfl_xor_sync(0xFFFFFFFFu, acc, off);
    if ((tid & 31) == 0) warpsum[tid >> 5] = acc;
    __syncthreads();

    if (tid < 32) {
        float v = (tid < BLOCK / 32) ? warpsum[tid] : 0.0f;
#pragma unroll
        for (int off = 4; off > 0; off >>= 1)
            v += __shfl_xor_sync(0xFFFFFFFFu, v, off);
        if (tid == 0) {
            // Diagonal tiles double-count unordered pairs (plus self terms) -> halve.
            g_partials[blockIdx.x] = (it == jt) ? 0.5f * v : v;
            __threadfence();
            unsigned int ticket = atomicAdd(&g_count, 1u);
            isLast = (ticket == NCTA - 1);
        }
    }
    __syncthreads();

    // Last block: parallel deterministic reduction of the 576 partials.
    if (isLast) {
        __threadfence();
        float v = g_partials[tid] + g_partials[tid + BLOCK];
        if (tid < NCTA - 2 * BLOCK)          // 64 leftovers
            v += g_partials[tid + 2 * BLOCK];
#pragma unroll
        for (int off = 16; off > 0; off >>= 1)
            v += __shfl_xor_sync(0xFFFFFFFFu, v, off);
        if ((tid & 31) == 0) warpsum[tid >> 5] = v;
        __syncthreads();
        if (tid == 0) {
            float s = 0.0f;
#pragma unroll
            for (int w = 0; w < BLOCK / 32; ++w) s += warpsum[w];
            // Each diagonal self-pair contributed 0.5 * relu(2)^2 = 2 -> subtract 2*N.
            out[0] = s - 2.0f * (float)NMOV;
            g_count = 0;   // reset for next graph replay
        }
    }
}

extern "C" void kernel_launch(void* const* d_in, const int* in_sizes, int n_in,
                              void* d_out, int out_size)
{
    (void)in_sizes; (void)n_in; (void)out_size;
    const float* pos = (const float*)d_in[0];
    // d_in[1] is macro_mask (bool) — all-true, unused by the computation.
    const float* sx  = (const float*)d_in[2];
    const float* sy  = (const float*)d_in[3];
    float* out = (float*)d_out;

    notch_rt2<<<NCTA, BLOCK>>>(pos, sx, sy, out);
}